// round 13
// baseline (speedup 1.0000x reference)
#include <cuda_runtime.h>

// Problem constants (fixed by the dataset)
#define Bc   2
#define Sc   4096
#define Hc   12
#define Gc   64
#define Wc   513
#define WGc  577      // G + W
#define HALF 256      // W/2
#define BSc  (Bc * Sc)

#define N_SPLIT         16           // s-splits per 128-wide i-tile
#define N_TILES         (Bc * 32)    // 128-wide i-tiles
#define N_LOCAL_BLOCKS  (N_TILES * N_SPLIT)   // 1024
#define N_GCHUNK        96           // row-chunks per batch for global sums
#define N_GLOBAL_BLOCKS (Bc * N_GCHUNK)       // 192
// main grid = 1216 = 8 * 152 -> fully resident in one wave on GB300

// Scratch. Zero-initialized at module load (.bss); final_kernel re-zeroes it
// after consuming, so every kernel_launch call (and every graph replay) sees
// zeros. Plain __device__ globals -> allocation-free.
__device__ float g_probs_sum[BSc];          // accumulated local sums
__device__ float g_gs[Bc][Bc * Gc];         // global sums, one copy per consumer

// ---------------------------------------------------------------------------
// Fused main pass: reads all 227 MB of probs exactly once. DRAM-bound.
//
// Local role (blocks 0..1023), gather formulation:
//   local_sum[b,i] = sum_{s} sum_h probs[b,s,h, 320+i-s],  c in [64,577)
//   Block owns 128 consecutive i (4 warps side-by-side) -> for each (s,h)
//   the block loads a CONTIGUOUS 512B span. BRANCHLESS body: out-of-range
//   (s,c) are clamped to legal addresses and zeroed via flag multiply, so
//   ptxas can software-pipeline loads across the x2-unrolled t-loop
//   (24 loads in flight/thread -> closes the DRAM demand gap seen in ncu).
// Global role (blocks 1024..1215):
//   global_sum[b,c] = sum_{s,h} probs[b,s,h,c], c < 64; atomicAdd into both
//   g_gs copies (each final block consumes+zeroes its own copy -> no race).
// ---------------------------------------------------------------------------
__global__ __launch_bounds__(256) void main_kernel(
    const float* __restrict__ probs, const float* __restrict__ mask)
{
    if (blockIdx.x < N_LOCAL_BLOCKS) {
        const int tile  = blockIdx.x >> 4;    // 0..63
        const int split = blockIdx.x & 15;    // 0..15
        const int w     = threadIdx.x >> 5;   // 0..7
        const int lane  = threadIdx.x & 31;
        const int iw    = w & 3;              // i-subtile within block
        const int sg    = w >> 2;             // s-subgroup (0,1)

        const int b  = tile >> 5;             // 32 tiles per batch
        const int i0 = (tile & 31) << 7;      // i base (128-wide tile)
        const int i  = i0 + iw * 32 + lane;   // this thread's output token

        // s-window for this tile: [i0-256, i0+384), 640 values = 16*2*20
        const int s_start = i0 - HALF + split * 40 + sg * 20;

        const float* __restrict__ mrow = mask + b * Sc;
        const float* __restrict__ pbase =
            probs + (size_t)b * Sc * Hc * WGc;
        float acc = 0.0f;

        #pragma unroll 2
        for (int t = 0; t < 20; ++t) {
            const int s = s_start + t;
            const int c = Gc + HALF + i - s;           // column for this i
            const bool ok = (s >= 0) && (s < Sc) && (c >= Gc) && (c < WGc);
            const int  sc_ = min(max(s, 0), Sc - 1);   // clamped (legal) addr
            const int  cc_ = min(max(c, Gc), WGc - 1);
            const float flag =
                (ok && (mrow[sc_] >= 0.0f)) ? 1.0f : 0.0f;
            const float* __restrict__ row =
                pbase + (size_t)sc_ * Hc * WGc + cc_;
            float a = 0.0f;
            #pragma unroll
            for (int h = 0; h < Hc; ++h)               // 12 independent loads
                a += row[(size_t)h * WGc];
            acc += flag * a;
        }

        __shared__ float red[2][4][33];
        red[sg][iw][lane] = acc;
        __syncthreads();
        if (sg == 0)                                    // warps 0..3 emit
            atomicAdd(&g_probs_sum[b * Sc + i],
                      red[0][iw][lane] + red[1][iw][lane]);
    } else {
        const int idx   = blockIdx.x - N_LOCAL_BLOCKS;  // 0..191
        const int b     = idx / N_GCHUNK;
        const int chunk = idx % N_GCHUNK;
        const int c     = threadIdx.x & 63;
        const int rg    = threadIdx.x >> 6;

        const float* __restrict__ mrow = mask + b * Sc;
        const float* __restrict__ base = probs + (size_t)b * Sc * Hc * WGc;

        float acc = 0.0f;
        const int r0 = chunk * 512;      // rows are (s*H + h), 49152 per batch
        #pragma unroll 8
        for (int r = r0 + rg; r < r0 + 512; r += 4) {
            const int s = r / Hc;
            const float flag = (mrow[s] >= 0.0f) ? 1.0f : 0.0f;
            acc += flag * base[(size_t)r * WGc + c];
        }

        __shared__ float gred[4][64];
        gred[rg][c] = acc;
        __syncthreads();
        if (rg == 0) {
            const float tot = gred[0][c] + gred[1][c] + gred[2][c] + gred[3][c];
            atomicAdd(&g_gs[0][b * Gc + c], tot);   // copy for final block 0
            atomicAdd(&g_gs[1][b * Gc + c], tot);   // copy for final block 1
        }
    }
}

// ---------------------------------------------------------------------------
// Final: scatter + per-batch max + threshold + scratch re-zero.
// One block per batch, 1024 threads. Reads only 16KB (L2-hot) + 128 gs.
// ---------------------------------------------------------------------------
__global__ __launch_bounds__(1024) void final_kernel(
    const float* __restrict__ thr_p,
    const void* __restrict__ lbv, const void* __restrict__ liv,
    const void* __restrict__ gbv, const void* __restrict__ giv,
    int n, float* __restrict__ out)
{
    __shared__ float ps[Sc];           // probs_sum for this batch (16 KB)
    __shared__ float gs[Bc * Gc];      // global sums, BOTH batches
    __shared__ float smax[32];
    __shared__ int   is32;

    const int b   = blockIdx.x;
    const int tid = threadIdx.x;
    const int lane = tid & 31, wrp = tid >> 5;

    ((float4*)ps)[tid] = ((const float4*)(g_probs_sum + b * Sc))[tid];
    if (tid < Bc * Gc) gs[tid] = g_gs[b][tid];
    if (tid == 0) is32 = 0;
    __syncthreads();

    // Scratch is fully captured in smem now -> zero it for the next replay.
    ((float4*)(g_probs_sum + b * Sc))[tid] = make_float4(0.f, 0.f, 0.f, 0.f);
    if (tid < Bc * Gc) g_gs[b][tid] = 0.0f;

    // dtype detect on glob_i: int32 data viewed as int64 words yields values
    // outside [0, 2^31). Scan n/2 words (safe in either layout).
    if (tid < n / 2) {
        const long long v = ((const long long*)giv)[tid];
        if (v < 0 || v >= (1LL << 31)) atomicOr(&is32, 1);
    }
    __syncthreads();

    // scatter: probs_sum[lb, li] += global_sum[gb, gi]  (duplicates add)
    if (tid < n) {
        int lb, li, gb, gi;
        if (is32) {
            lb = ((const int*)lbv)[tid];
            li = ((const int*)liv)[tid];
            gb = ((const int*)gbv)[tid];
            gi = ((const int*)giv)[tid];
        } else {
            lb = (int)((const long long*)lbv)[tid];
            li = (int)((const long long*)liv)[tid];
            gb = (int)((const long long*)gbv)[tid];
            gi = (int)((const long long*)giv)[tid];
        }
        if (lb == b) atomicAdd(&ps[li], gs[gb * Gc + gi]);
    }
    __syncthreads();

    // per-batch max (4 values/thread, shuffle + smem reduce)
    const float4 v = ((const float4*)ps)[tid];
    float m = fmaxf(fmaxf(v.x, v.y), fmaxf(v.z, v.w));
    #pragma unroll
    for (int off = 16; off >= 1; off >>= 1)
        m = fmaxf(m, __shfl_xor_sync(0xffffffffu, m, off));
    if (lane == 0) smax[wrp] = m;
    __syncthreads();
    if (wrp == 0) {
        float mm = smax[lane];
        #pragma unroll
        for (int off = 16; off >= 1; off >>= 1)
            mm = fmaxf(mm, __shfl_xor_sync(0xffffffffu, mm, off));
        if (lane == 0) smax[0] = mm;
    }
    __syncthreads();
    const float pm  = smax[0];
    const float thr = fmaxf(1e-5f, thr_p[0]);

    // outputs: [ new_attention_mask (B*S) | scores (B*S) ], float4 stores
    const float4 sc = make_float4(v.x / pm, v.y / pm, v.z / pm, v.w / pm);
    float4 mk;
    mk.x = (sc.x < thr) ? -10000.0f : 0.0f;
    mk.y = (sc.y < thr) ? -10000.0f : 0.0f;
    mk.z = (sc.z < thr) ? -10000.0f : 0.0f;
    mk.w = (sc.w < thr) ? -10000.0f : 0.0f;
    ((float4*)(out + b * Sc))[tid]       = mk;
    ((float4*)(out + BSc + b * Sc))[tid] = sc;
}

// ---------------------------------------------------------------------------
// launch — 2 graph nodes, allocation-free.
// Inputs (metadata order): attention_mask f32, attention_probs f32,
// keep_threshold f32[1], max_num_global_attn_indices (unused),
// loc_b, loc_i, glob_b, glob_i.
// ---------------------------------------------------------------------------
extern "C" void kernel_launch(void* const* d_in, const int* in_sizes, int n_in,
                              void* d_out, int out_size)
{
    const float* mask  = (const float*)d_in[0];
    const float* probs = (const float*)d_in[1];
    const float* thr   = (const float*)d_in[2];
    const void*  lb    = d_in[4];
    const void*  li    = d_in[5];
    const void*  gb    = d_in[6];
    const void*  gi    = d_in[7];
    float* out = (float*)d_out;
    const int n_idx = in_sizes[4];

    main_kernel<<<N_LOCAL_BLOCKS + N_GLOBAL_BLOCKS, 256>>>(probs, mask);
    final_kernel<<<Bc, 1024>>>(thr, lb, li, gb, gi, n_idx, out);
}

// round 14
// speedup vs baseline: 1.0745x; 1.0745x over previous
#include <cuda_runtime.h>

// Problem constants (fixed by the dataset)
#define Bc   2
#define Sc   4096
#define Hc   12
#define Gc   64
#define Wc   513
#define WGc  577      // G + W
#define HALF 256      // W/2
#define BSc  (Bc * Sc)

#define N_SPLIT         16           // s-splits per 128-wide i-tile
#define N_TILES         (Bc * 32)    // 128-wide i-tiles
#define N_LOCAL_BLOCKS  (N_TILES * N_SPLIT)   // 1024
#define N_GCHUNK        96           // row-chunks per batch for global sums
#define N_GLOBAL_BLOCKS (Bc * N_GCHUNK)       // 192
// main grid = 1216 = 8 * 152 -> fully resident in one wave on GB300

#define N_IDX_MAX 128                // index arrays are B*G = 128 entries

// Scratch. Zero-initialized at module load (.bss); final_kernel re-zeroes it
// after consuming, so every kernel_launch call (and every graph replay) sees
// zeros. Plain __device__ globals -> allocation-free.
__device__ float g_probs_sum[BSc];          // accumulated local sums
__device__ float g_gs[Bc][Bc * Gc];         // global sums, one copy per consumer

// ---------------------------------------------------------------------------
// Fused main pass (UNCHANGED from the proven 44.6us R11 version):
// reads all 227 MB of probs exactly once. DRAM-bound.
// ---------------------------------------------------------------------------
__global__ __launch_bounds__(256) void main_kernel(
    const float* __restrict__ probs, const float* __restrict__ mask)
{
    if (blockIdx.x < N_LOCAL_BLOCKS) {
        const int tile  = blockIdx.x >> 4;    // 0..63
        const int split = blockIdx.x & 15;    // 0..15
        const int w     = threadIdx.x >> 5;   // 0..7
        const int lane  = threadIdx.x & 31;
        const int iw    = w & 3;              // i-subtile within block
        const int sg    = w >> 2;             // s-subgroup (0,1)

        const int b  = tile >> 5;             // 32 tiles per batch
        const int i0 = (tile & 31) << 7;      // i base (128-wide tile)
        const int i  = i0 + iw * 32 + lane;   // this thread's output token

        // s-window for this tile: [i0-256, i0+384), 640 values = 16*2*20
        const int s_start = i0 - HALF + split * 40 + sg * 20;

        const float* __restrict__ mrow = mask + b * Sc;
        float acc = 0.0f;

        #pragma unroll 1
        for (int t = 0; t < 20; ++t) {
            const int s = s_start + t;
            if (s < 0 || s >= Sc) continue;
            const int c = Gc + HALF + i - s;           // column for this i
            if (c < Gc || c >= WGc) continue;          // diagonal band edges
            const float flag = (mrow[s] >= 0.0f) ? 1.0f : 0.0f;
            const float* __restrict__ row =
                probs + (size_t)(b * Sc + s) * Hc * WGc + c;
            float a = 0.0f;
            #pragma unroll
            for (int h = 0; h < Hc; ++h)               // 12 independent loads
                a += row[(size_t)h * WGc];
            acc += flag * a;
        }

        __shared__ float red[2][4][33];
        red[sg][iw][lane] = acc;
        __syncthreads();
        if (sg == 0)                                    // warps 0..3 emit
            atomicAdd(&g_probs_sum[b * Sc + i],
                      red[0][iw][lane] + red[1][iw][lane]);
    } else {
        const int idx   = blockIdx.x - N_LOCAL_BLOCKS;  // 0..191
        const int b     = idx / N_GCHUNK;
        const int chunk = idx % N_GCHUNK;
        const int c     = threadIdx.x & 63;
        const int rg    = threadIdx.x >> 6;

        const float* __restrict__ mrow = mask + b * Sc;
        const float* __restrict__ base = probs + (size_t)b * Sc * Hc * WGc;

        float acc = 0.0f;
        const int r0 = chunk * 512;      // rows are (s*H + h), 49152 per batch
        #pragma unroll 8
        for (int r = r0 + rg; r < r0 + 512; r += 4) {
            const int s = r / Hc;
            const float flag = (mrow[s] >= 0.0f) ? 1.0f : 0.0f;
            acc += flag * base[(size_t)r * WGc + c];
        }

        __shared__ float gred[4][64];
        gred[rg][c] = acc;
        __syncthreads();
        if (rg == 0) {
            const float tot = gred[0][c] + gred[1][c] + gred[2][c] + gred[3][c];
            atomicAdd(&g_gs[0][b * Gc + c], tot);   // copy for final block 0
            atomicAdd(&g_gs[1][b * Gc + c], tot);   // copy for final block 1
        }
    }
}

// ---------------------------------------------------------------------------
// Final: scatter + per-batch max + threshold + scratch re-zero.
// One block per batch, 1024 threads. LATENCY-OPTIMIZED: all independent
// global loads (ps, gs, raw index words) issue before the first sync; index
// decode happens from smem, so only ONE extra conditional load phase remains
// (int64 upper halves). Everything after that is smem-only.
// ---------------------------------------------------------------------------
__global__ __launch_bounds__(1024) void final_kernel(
    const float* __restrict__ thr_p,
    const void* __restrict__ lbv, const void* __restrict__ liv,
    const void* __restrict__ gbv, const void* __restrict__ giv,
    int n, float* __restrict__ out)
{
    __shared__ float     ps[Sc];             // probs_sum for this batch (16 KB)
    __shared__ float     gs[Bc * Gc];        // global sums, BOTH batches
    __shared__ long long sidx[4][N_IDX_MAX]; // staged index words (4 KB)
    __shared__ float     smax[32];
    __shared__ int       is32;

    const int b   = blockIdx.x;
    const int tid = threadIdx.x;
    const int lane = tid & 31, wrp = tid >> 5;
    const void* const parr[4] = { lbv, liv, gbv, giv };

    // ---- phase 1: ALL independent loads issue back-to-back ----
    ((float4*)ps)[tid] = ((const float4*)(g_probs_sum + b * Sc))[tid];
    if (tid < Bc * Gc) gs[tid] = g_gs[b][tid];
    // raw 8-byte words, first n/2 of each array: covers the ENTIRE buffer if
    // dtype is int32 (n*4 bytes), the lower half if int64. Safe either way.
    int detect = 0;
    if (tid < 4 * (n / 2)) {
        const int a = tid / (n / 2), k = tid % (n / 2);
        const long long v = ((const long long*)parr[a])[k];
        sidx[a][k] = v;
        // dtype detect on glob_i words: int32 data viewed as int64 yields
        // values outside [0, 2^31).
        if (a == 3 && (v < 0 || v >= (1LL << 31))) detect = 1;
    }
    if (tid == 0) is32 = 0;
    __syncthreads();
    if (detect) atomicOr(&is32, 1);
    __syncthreads();

    // ---- phase 2 (int64 only): upper-half words ----
    if (!is32 && tid < 4 * (n / 2)) {
        const int a = tid / (n / 2), k = n / 2 + tid % (n / 2);
        sidx[a][k] = ((const long long*)parr[a])[k];
    }
    // scratch re-zero (fire-and-forget stores, off the critical path)
    ((float4*)(g_probs_sum + b * Sc))[tid] = make_float4(0.f, 0.f, 0.f, 0.f);
    if (tid < Bc * Gc) g_gs[b][tid] = 0.0f;
    __syncthreads();

    // ---- scatter: probs_sum[lb, li] += global_sum[gb, gi] (smem-only) ----
    if (tid < n) {
        int lb, li, gb, gi;
        if (is32) {
            lb = ((const int*)sidx[0])[tid];
            li = ((const int*)sidx[1])[tid];
            gb = ((const int*)sidx[2])[tid];
            gi = ((const int*)sidx[3])[tid];
        } else {
            lb = (int)sidx[0][tid];
            li = (int)sidx[1][tid];
            gb = (int)sidx[2][tid];
            gi = (int)sidx[3][tid];
        }
        if (lb == b) atomicAdd(&ps[li], gs[gb * Gc + gi]);
    }
    __syncthreads();

    // ---- per-batch max (4 values/thread, shuffle + smem reduce) ----
    const float4 v = ((const float4*)ps)[tid];
    float m = fmaxf(fmaxf(v.x, v.y), fmaxf(v.z, v.w));
    #pragma unroll
    for (int off = 16; off >= 1; off >>= 1)
        m = fmaxf(m, __shfl_xor_sync(0xffffffffu, m, off));
    if (lane == 0) smax[wrp] = m;
    __syncthreads();
    if (wrp == 0) {
        float mm = smax[lane];
        #pragma unroll
        for (int off = 16; off >= 1; off >>= 1)
            mm = fmaxf(mm, __shfl_xor_sync(0xffffffffu, mm, off));
        if (lane == 0) smax[0] = mm;
    }
    __syncthreads();
    const float pm  = smax[0];
    const float thr = fmaxf(1e-5f, thr_p[0]);

    // ---- outputs: [ new_attention_mask (B*S) | scores (B*S) ] ----
    const float4 sc = make_float4(v.x / pm, v.y / pm, v.z / pm, v.w / pm);
    float4 mk;
    mk.x = (sc.x < thr) ? -10000.0f : 0.0f;
    mk.y = (sc.y < thr) ? -10000.0f : 0.0f;
    mk.z = (sc.z < thr) ? -10000.0f : 0.0f;
    mk.w = (sc.w < thr) ? -10000.0f : 0.0f;
    ((float4*)(out + b * Sc))[tid]       = mk;
    ((float4*)(out + BSc + b * Sc))[tid] = sc;
}

// ---------------------------------------------------------------------------
// launch — 2 graph nodes, allocation-free.
// Inputs (metadata order): attention_mask f32, attention_probs f32,
// keep_threshold f32[1], max_num_global_attn_indices (unused),
// loc_b, loc_i, glob_b, glob_i.
// ---------------------------------------------------------------------------
extern "C" void kernel_launch(void* const* d_in, const int* in_sizes, int n_in,
                              void* d_out, int out_size)
{
    const float* mask  = (const float*)d_in[0];
    const float* probs = (const float*)d_in[1];
    const float* thr   = (const float*)d_in[2];
    const void*  lb    = d_in[4];
    const void*  li    = d_in[5];
    const void*  gb    = d_in[6];
    const void*  gi    = d_in[7];
    float* out = (float*)d_out;
    const int n_idx = in_sizes[4];

    main_kernel<<<N_LOCAL_BLOCKS + N_GLOBAL_BLOCKS, 256>>>(probs, mask);
    final_kernel<<<Bc, 1024>>>(thr, lb, li, gb, gi, n_idx, out);
}